// round 2
// baseline (speedup 1.0000x reference)
#include <cuda_runtime.h>
#include <cuda_bf16.h>
#include <cstddef>

// Problem constants
#define BATCH 4
#define NSEQ 2048
#define DIM 512
#define NHEAD 8
#define DHEAD 128
#define INNER 1024          // NHEAD*DHEAD
#define MROWS (BATCH*NSEQ)  // 8192

// Gaussian window half-width: sigma<=2.5 -> exp(-32^2/(2*6.25)) ~ 1e-36, safely negligible
#define WIN 32
#define TN 64               // n-rows per smoothing block

// Scratch (allocation-free rule: __device__ globals)
__device__ float g_y[MROWS * INNER];   // x @ Wg
__device__ float g_s[MROWS * INNER];   // smoothed

typedef unsigned long long ull;

__device__ __forceinline__ ull pack_dup(float a) {
    ull r; asm("mov.b64 %0, {%1, %1};" : "=l"(r) : "f"(a)); return r;
}
__device__ __forceinline__ void ffma2(ull& d, ull a, ull b) {
    asm("fma.rn.f32x2 %0, %1, %2, %0;" : "+l"(d) : "l"(a), "l"(b));
}
__device__ __forceinline__ void unpack2(ull v, float& lo, float& hi) {
    asm("mov.b64 {%0, %1}, %2;" : "=f"(lo), "=f"(hi) : "l"(v));
}

// ---------------------------------------------------------------------------
// 128x128 tiled fp32 GEMM, C = A[M,K] * B[K,N], row-major, using packed f32x2 FMA.
// 256 threads, 8x8 microtile per thread, K-tile = 16, reg-prefetch of next tile.
// Requires M%128==0, N%128==0, K%16==0 (true for all calls here).
// ---------------------------------------------------------------------------
__global__ __launch_bounds__(256, 2)
void gemm128_f32x2(const float* __restrict__ A, const float* __restrict__ B,
                   float* __restrict__ C, int M, int N, int K) {
    __shared__ float As[16][132];   // transposed A tile, padded to cut STS conflicts
    __shared__ float Bs[16][128];

    const int tid = threadIdx.x;
    const int tx = tid & 15;
    const int ty = tid >> 4;
    const int row0 = blockIdx.y << 7;
    const int col0 = blockIdx.x << 7;

    // A tile load mapping: 128 rows x 16 k as 512 float4; thread does idx=tid (rows 0..63)
    // and idx=tid+256 (rows 64..127)
    const int ar0 = tid >> 2;            // 0..63
    const int akc = (tid & 3) << 2;      // k chunk 0,4,8,12
    // B tile load mapping: 16 k x 128 cols as 512 float4
    const int bk0 = tid >> 5;            // 0..7
    const int bjc = (tid & 31) << 2;     // col chunk

    ull acc[8][4];
#pragma unroll
    for (int i = 0; i < 8; i++)
#pragma unroll
        for (int j = 0; j < 4; j++) acc[i][j] = 0ULL;

    const int ktiles = K >> 4;

    float4 ra0, ra1, rb0, rb1;
    {
        const float* Ap = A + (size_t)row0 * K;
        ra0 = *(const float4*)(Ap + (size_t)ar0 * K + akc);
        ra1 = *(const float4*)(Ap + (size_t)(ar0 + 64) * K + akc);
        const float* Bp = B + col0;
        rb0 = *(const float4*)(Bp + (size_t)bk0 * N + bjc);
        rb1 = *(const float4*)(Bp + (size_t)(bk0 + 8) * N + bjc);
    }

    for (int kt = 0; kt < ktiles; kt++) {
        // scatter A (transposed) and store B
        As[akc + 0][ar0] = ra0.x; As[akc + 1][ar0] = ra0.y;
        As[akc + 2][ar0] = ra0.z; As[akc + 3][ar0] = ra0.w;
        As[akc + 0][ar0 + 64] = ra1.x; As[akc + 1][ar0 + 64] = ra1.y;
        As[akc + 2][ar0 + 64] = ra1.z; As[akc + 3][ar0 + 64] = ra1.w;
        *(float4*)&Bs[bk0][bjc]     = rb0;
        *(float4*)&Bs[bk0 + 8][bjc] = rb1;
        __syncthreads();

        if (kt + 1 < ktiles) {
            const int k0 = (kt + 1) << 4;
            const float* Ap = A + (size_t)row0 * K + k0;
            ra0 = *(const float4*)(Ap + (size_t)ar0 * K + akc);
            ra1 = *(const float4*)(Ap + (size_t)(ar0 + 64) * K + akc);
            const float* Bp = B + (size_t)k0 * N + col0;
            rb0 = *(const float4*)(Bp + (size_t)bk0 * N + bjc);
            rb1 = *(const float4*)(Bp + (size_t)(bk0 + 8) * N + bjc);
        }

#pragma unroll
        for (int k = 0; k < 16; k++) {
            float4 a0 = *(const float4*)&As[k][ty << 3];
            float4 a1 = *(const float4*)&As[k][(ty << 3) + 4];
            const ulonglong2* bp = (const ulonglong2*)&Bs[k][tx << 3];
            ulonglong2 b01 = bp[0];
            ulonglong2 b23 = bp[1];
            float av[8] = {a0.x, a0.y, a0.z, a0.w, a1.x, a1.y, a1.z, a1.w};
#pragma unroll
            for (int i = 0; i < 8; i++) {
                ull ap = pack_dup(av[i]);
                ffma2(acc[i][0], ap, b01.x);
                ffma2(acc[i][1], ap, b01.y);
                ffma2(acc[i][2], ap, b23.x);
                ffma2(acc[i][3], ap, b23.y);
            }
        }
        __syncthreads();
    }

    // epilogue
    float* Cp = C + (size_t)(row0 + (ty << 3)) * N + col0 + (tx << 3);
#pragma unroll
    for (int r = 0; r < 8; r++) {
        float o[8];
#pragma unroll
        for (int j = 0; j < 4; j++) unpack2(acc[r][j], o[2 * j], o[2 * j + 1]);
        *(float4*)(Cp + (size_t)r * N)     = make_float4(o[0], o[1], o[2], o[3]);
        *(float4*)(Cp + (size_t)r * N + 4) = make_float4(o[4], o[5], o[6], o[7]);
    }
}

// ---------------------------------------------------------------------------
// Gaussian banded smoothing along n, per head, row-normalized.
// grid: (NSEQ/TN, 2 channel-halves, BATCH*NHEAD), 256 threads.
// s[b,n,h*128+c] = (1/Z(n)) * sum_{j=0..64} ew[j] * y[b, n-WIN+j, h*128+c]
// ---------------------------------------------------------------------------
__global__ __launch_bounds__(256)
void smooth_kernel(const float* __restrict__ y, float* __restrict__ s,
                   const float* __restrict__ sigma) {
    __shared__ float yt[TN + 2 * WIN][64];   // 128 rows x 64 channels
    __shared__ float ew[2 * WIN + 1];
    __shared__ float invZ[TN];

    const int n0   = blockIdx.x * TN;
    const int half = blockIdx.y;
    const int bh   = blockIdx.z;
    const int b    = bh >> 3;            // / NHEAD
    const int h    = bh & 7;
    const int tid  = threadIdx.x;

    const float* ybase = y + (size_t)b * NSEQ * INNER + h * DHEAD + half * 64;

    // load 128 rows x 64 channels (16 float4 per row); zero out-of-range rows
    for (int i = tid; i < 128 * 16; i += 256) {
        const int r = i >> 4;
        const int c = (i & 15) << 2;
        const int m = n0 - WIN + r;
        float4 v = make_float4(0.f, 0.f, 0.f, 0.f);
        if (m >= 0 && m < NSEQ) v = *(const float4*)(ybase + (size_t)m * INNER + c);
        *(float4*)&yt[r][c] = v;
    }

    if (tid < 2 * WIN + 1) {
        const float sg = sigma[h];
        const float d  = (float)(tid - WIN);
        ew[tid] = __expf(-d * d / (2.f * sg * sg));
    }
    __syncthreads();

    if (tid < TN) {
        const int n = n0 + tid;
        float z = 0.f;
#pragma unroll
        for (int j = 0; j <= 2 * WIN; j++) {
            const int m = n - WIN + j;
            if (m >= 0 && m < NSEQ) z += ew[j];
        }
        invZ[tid] = 1.f / z;
    }
    __syncthreads();

    // compute: channel-pair per thread; 8 t-rows per thread
    const int cp = tid & 31;     // channel pair 0..31
    const int tg = tid >> 5;     // 0..7
#pragma unroll
    for (int k = 0; k < 8; k++) {
        const int t = tg * 8 + k;
        float ax = 0.f, ay = 0.f;
#pragma unroll
        for (int j = 0; j <= 2 * WIN; j++) {
            const float w = ew[j];
            const float2 v = *(const float2*)&yt[t + j][cp << 1];
            ax = fmaf(w, v.x, ax);
            ay = fmaf(w, v.y, ay);
        }
        const float iz = invZ[t];
        const int n = n0 + t;
        float2* outp = (float2*)(s + ((size_t)b * NSEQ + n) * INNER
                                 + h * DHEAD + half * 64 + (cp << 1));
        *outp = make_float2(ax * iz, ay * iz);
    }
}

// ---------------------------------------------------------------------------
extern "C" void kernel_launch(void* const* d_in, const int* in_sizes, int n_in,
                              void* d_out, int out_size) {
    const float* x     = (const float*)d_in[0];
    const float* Wg    = (const float*)d_in[1];
    const float* Wout  = (const float*)d_in[2];
    const float* sigma = (const float*)d_in[3];
    float* out = (float*)d_out;

    float* y = nullptr;
    float* s = nullptr;
    cudaGetSymbolAddress((void**)&y, g_y);
    cudaGetSymbolAddress((void**)&s, g_s);

    // GEMM1: y[8192,1024] = x[8192,512] @ Wg[512,1024]
    gemm128_f32x2<<<dim3(INNER / 128, MROWS / 128), 256>>>(x, Wg, y, MROWS, INNER, DIM);

    // Gaussian banded attention (row-normalized local smoothing per head)
    smooth_kernel<<<dim3(NSEQ / TN, 2, BATCH * NHEAD), 256>>>(y, s, sigma);

    // GEMM2: out[8192,512] = s[8192,1024] @ Wout[1024,512]
    gemm128_f32x2<<<dim3(DIM / 128, MROWS / 128), 256>>>(s, Wout, out, MROWS, DIM, INNER);
}

// round 4
// speedup vs baseline: 1.8598x; 1.8598x over previous
#include <cuda_runtime.h>
#include <cuda_bf16.h>
#include <cstdint>
#include <cstddef>

// Problem constants
#define BATCH 4
#define NSEQ 2048
#define DIM 512
#define NHEAD 8
#define DHEAD 128
#define INNER 1024
#define MROWS (BATCH*NSEQ)  // 8192

#define WIN 32
#define TN 64

// ---------------- scratch (allocation-free rule) ----------------
__device__ __align__(16) float          g_y[MROWS * INNER];
__device__ __align__(16) __nv_bfloat16  g_xhi[MROWS * DIM];
__device__ __align__(16) __nv_bfloat16  g_xlo[MROWS * DIM];
__device__ __align__(16) __nv_bfloat16  g_shi[MROWS * INNER];
__device__ __align__(16) __nv_bfloat16  g_slo[MROWS * INNER];
__device__ __align__(16) __nv_bfloat16  g_wgT_hi[INNER * DIM];   // Wg^T  [1024,512]
__device__ __align__(16) __nv_bfloat16  g_wgT_lo[INNER * DIM];
__device__ __align__(16) __nv_bfloat16  g_woT_hi[DIM * INNER];   // Wout^T [512,1024]
__device__ __align__(16) __nv_bfloat16  g_woT_lo[DIM * INNER];

// ---------------- PTX helpers (base sm_103-safe: sm_80-era ISA) ------------
__device__ __forceinline__ uint32_t smem_to_u32(const void* p) {
    uint32_t a;
    asm("{ .reg .u64 t; cvta.to.shared.u64 t, %1; cvt.u32.u64 %0, t; }" : "=r"(a) : "l"(p));
    return a;
}
__device__ __forceinline__ void cp16(uint32_t dst, const void* src) {
    asm volatile("cp.async.cg.shared.global [%0], [%1], 16;" :: "r"(dst), "l"(src) : "memory");
}
#define CP_COMMIT() asm volatile("cp.async.commit_group;" ::: "memory")
#define CP_WAIT1()  asm volatile("cp.async.wait_group 1;" ::: "memory")

__device__ __forceinline__ void ldsm_x4(uint32_t addr, uint32_t& r0, uint32_t& r1,
                                        uint32_t& r2, uint32_t& r3) {
    asm volatile("ldmatrix.sync.aligned.m8n8.x4.shared.b16 {%0,%1,%2,%3}, [%4];"
                 : "=r"(r0), "=r"(r1), "=r"(r2), "=r"(r3) : "r"(addr));
}
__device__ __forceinline__ void mma16816(float* d, const uint32_t* a,
                                         uint32_t b0, uint32_t b1) {
    asm volatile("mma.sync.aligned.m16n8k16.row.col.f32.bf16.bf16.f32 "
                 "{%0,%1,%2,%3}, {%4,%5,%6,%7}, {%8,%9}, {%0,%1,%2,%3};"
                 : "+f"(d[0]), "+f"(d[1]), "+f"(d[2]), "+f"(d[3])
                 : "r"(a[0]), "r"(a[1]), "r"(a[2]), "r"(a[3]), "r"(b0), "r"(b1));
}

// ---------------------------------------------------------------------------
// HMMA GEMM: C[M,N](f32) = (Ahi+Alo)[M,K] @ (Bhi+Blo)^T,  B* stored [N,K].
// CTA tile 128x64, K-chunk 32, 8 warps, warp tile 32x32 (2 m16 x 4 n8 atoms).
// Products hi*hi + hi*lo + lo*hi accumulated in f32 registers.
// 2-stage cp.async pipeline. SMEM rows padded to 80B (conflict rotation).
// ---------------------------------------------------------------------------
#define CTM 128
#define CTN 64
#define TK  32
#define ROWB 80
#define STG_A (CTM * ROWB)               // 10240
#define STG_B (CTN * ROWB)               // 5120
#define STAGE_BYTES (2 * STG_A + 2 * STG_B)  // 30720
#define SMEM_GEMM (2 * STAGE_BYTES)          // 61440

__global__ __launch_bounds__(256, 2)
void gemm_mma(const __nv_bfloat16* __restrict__ Ahi, const __nv_bfloat16* __restrict__ Alo,
              const __nv_bfloat16* __restrict__ Bhi, const __nv_bfloat16* __restrict__ Blo,
              float* __restrict__ C, int M, int N, int K) {
    extern __shared__ char smem[];
    const uint32_t sb = smem_to_u32(smem);
    const int tid = threadIdx.x;
    const int wid = tid >> 5;
    const int lane = tid & 31;
    const int row0 = blockIdx.y << 7;
    const int col0 = blockIdx.x << 6;

    const int wm = wid & 3;       // warp m index (0..3) -> 32 rows each
    const int wn = wid >> 2;      // warp n index (0..1) -> 32 cols each
    const int m0 = wm << 5;
    const int n0 = wn << 5;

    // cp.async load mapping (per stage): A* rows 0..127, 4x16B chunks; B* rows 0..63
    const int arow = tid >> 2;          // 0..63 (plus +64 on second pass)
    const int ac   = (tid & 3) << 3;    // element offset within TK (0,8,16,24)
    const int acB  = (tid & 3) << 4;    // byte chunk (0,16,32,48)

    auto load_stage = [&](int buf, int kc) {
        const uint32_t st = sb + buf * STAGE_BYTES;
#pragma unroll
        for (int r = 0; r < 2; r++) {
            const int row = arow + 64 * r;
            const uint32_t d = st + row * ROWB + acB;
            const size_t e = (size_t)(row0 + row) * K + kc + ac;
            cp16(d, Ahi + e);
            cp16(d + STG_A, Alo + e);
        }
        {
            const uint32_t d = st + 2 * STG_A + arow * ROWB + acB;
            const size_t e = (size_t)(col0 + arow) * K + kc + ac;
            cp16(d, Bhi + e);
            cp16(d + STG_B, Blo + e);
        }
    };

    float d[2][4][4];
#pragma unroll
    for (int i = 0; i < 2; i++)
#pragma unroll
        for (int j = 0; j < 4; j++)
#pragma unroll
            for (int q = 0; q < 4; q++) d[i][j][q] = 0.f;

    const int KT = K / TK;
    load_stage(0, 0);
    CP_COMMIT();

    // ldmatrix lane addressing (constant per thread, add stage/base offsets)
    const uint32_t a_lane_off = (uint32_t)((lane & 15) * ROWB + ((lane >> 4) << 4));
    const uint32_t b_lane_off = (uint32_t)((((lane >> 4) << 3) + (lane & 7)) * ROWB
                                           + (((lane >> 3) & 1) << 4));

    for (int kt = 0; kt < KT; kt++) {
        if (kt + 1 < KT) load_stage((kt + 1) & 1, (kt + 1) * TK);
        CP_COMMIT();
        CP_WAIT1();
        __syncthreads();

        const uint32_t st = sb + (kt & 1) * STAGE_BYTES;
#pragma unroll
        for (int s = 0; s < 2; s++) {
            uint32_t ah[2][4], al[2][4], bh[2][4], bl[2][4];
#pragma unroll
            for (int i = 0; i < 2; i++) {
                const uint32_t aa = st + (uint32_t)((m0 + i * 16) * ROWB + s * 32) + a_lane_off;
                ldsm_x4(aa, ah[i][0], ah[i][1], ah[i][2], ah[i][3]);
                ldsm_x4(aa + STG_A, al[i][0], al[i][1], al[i][2], al[i][3]);
            }
#pragma unroll
            for (int g = 0; g < 2; g++) {
                const uint32_t ba = st + 2 * STG_A
                                  + (uint32_t)((n0 + g * 16) * ROWB + s * 32) + b_lane_off;
                ldsm_x4(ba, bh[g][0], bh[g][1], bh[g][2], bh[g][3]);
                ldsm_x4(ba + STG_B, bl[g][0], bl[g][1], bl[g][2], bl[g][3]);
            }
#pragma unroll
            for (int i = 0; i < 2; i++)
#pragma unroll
                for (int g = 0; g < 2; g++)
#pragma unroll
                    for (int jj = 0; jj < 2; jj++) {
                        const int j = g * 2 + jj;
                        mma16816(d[i][j], ah[i], bh[g][jj * 2], bh[g][jj * 2 + 1]);
                        mma16816(d[i][j], ah[i], bl[g][jj * 2], bl[g][jj * 2 + 1]);
                        mma16816(d[i][j], al[i], bh[g][jj * 2], bh[g][jj * 2 + 1]);
                    }
        }
        __syncthreads();
    }

    // epilogue: d[i][j] atom -> rows (groupID, groupID+8), cols (tig*2, +1)
    const int gr = lane >> 2;
    const int tg = lane & 3;
#pragma unroll
    for (int i = 0; i < 2; i++) {
        const int r0 = row0 + m0 + i * 16 + gr;
#pragma unroll
        for (int j = 0; j < 4; j++) {
            const int c = col0 + n0 + j * 8 + tg * 2;
            *(float2*)&C[(size_t)r0 * N + c]       = make_float2(d[i][j][0], d[i][j][1]);
            *(float2*)&C[(size_t)(r0 + 8) * N + c] = make_float2(d[i][j][2], d[i][j][3]);
        }
    }
}

// ---------------------------------------------------------------------------
// fp32 -> (hi, lo) bf16 split, vectorized
// ---------------------------------------------------------------------------
__global__ __launch_bounds__(256)
void split_kernel(const float* __restrict__ in, __nv_bfloat16* __restrict__ hi,
                  __nv_bfloat16* __restrict__ lo, int n4) {
    const int i = blockIdx.x * 256 + threadIdx.x;
    if (i >= n4) return;
    const float4 v = ((const float4*)in)[i];
    float f[4] = {v.x, v.y, v.z, v.w};
    __nv_bfloat16 h[4], l[4];
#pragma unroll
    for (int j = 0; j < 4; j++) {
        h[j] = __float2bfloat16(f[j]);
        l[j] = __float2bfloat16(f[j] - __bfloat162float(h[j]));
    }
    ((__nv_bfloat162*)hi)[2 * i]     = __nv_bfloat162(h[0], h[1]);
    ((__nv_bfloat162*)hi)[2 * i + 1] = __nv_bfloat162(h[2], h[3]);
    ((__nv_bfloat162*)lo)[2 * i]     = __nv_bfloat162(l[0], l[1]);
    ((__nv_bfloat162*)lo)[2 * i + 1] = __nv_bfloat162(l[2], l[3]);
}

// ---------------------------------------------------------------------------
// W[K,N] f32 -> W^T hi/lo bf16 [N,K]
// ---------------------------------------------------------------------------
__global__ __launch_bounds__(256)
void transpose_split(const float* __restrict__ in, __nv_bfloat16* __restrict__ hiT,
                     __nv_bfloat16* __restrict__ loT, int K, int N) {
    __shared__ float t[32][33];
    const int tx = threadIdx.x, ty = threadIdx.y;
    const int n0 = blockIdx.x * 32, k0 = blockIdx.y * 32;
#pragma unroll
    for (int i = 0; i < 4; i++)
        t[ty + 8 * i][tx] = in[(size_t)(k0 + ty + 8 * i) * N + n0 + tx];
    __syncthreads();
#pragma unroll
    for (int i = 0; i < 4; i++) {
        const float v = t[tx][ty + 8 * i];
        const __nv_bfloat16 h = __float2bfloat16(v);
        const __nv_bfloat16 l = __float2bfloat16(v - __bfloat162float(h));
        const size_t o = (size_t)(n0 + ty + 8 * i) * K + k0 + tx;
        hiT[o] = h;
        loT[o] = l;
    }
}

// ---------------------------------------------------------------------------
// Gaussian banded smoothing, row-normalized; emits bf16 hi/lo split directly.
// ---------------------------------------------------------------------------
__global__ __launch_bounds__(256)
void smooth_kernel(const float* __restrict__ y, __nv_bfloat16* __restrict__ shi,
                   __nv_bfloat16* __restrict__ slo, const float* __restrict__ sigma) {
    __shared__ float yt[TN + 2 * WIN][64];
    __shared__ float ew[2 * WIN + 1];
    __shared__ float invZ[TN];

    const int n0 = blockIdx.x * TN;
    const int half = blockIdx.y;
    const int bh = blockIdx.z;
    const int b = bh >> 3;
    const int h = bh & 7;
    const int tid = threadIdx.x;

    const float* ybase = y + (size_t)b * NSEQ * INNER + h * DHEAD + half * 64;
    for (int i = tid; i < 128 * 16; i += 256) {
        const int r = i >> 4;
        const int c = (i & 15) << 2;
        const int m = n0 - WIN + r;
        float4 v = make_float4(0.f, 0.f, 0.f, 0.f);
        if (m >= 0 && m < NSEQ) v = *(const float4*)(ybase + (size_t)m * INNER + c);
        *(float4*)&yt[r][c] = v;
    }
    if (tid < 2 * WIN + 1) {
        const float sg = sigma[h];
        const float dd = (float)(tid - WIN);
        ew[tid] = __expf(-dd * dd / (2.f * sg * sg));
    }
    __syncthreads();
    if (tid < TN) {
        const int n = n0 + tid;
        float z = 0.f;
#pragma unroll
        for (int j = 0; j <= 2 * WIN; j++) {
            const int m = n - WIN + j;
            if (m >= 0 && m < NSEQ) z += ew[j];
        }
        invZ[tid] = 1.f / z;
    }
    __syncthreads();

    const int cp = tid & 31;
    const int tg = tid >> 5;
#pragma unroll
    for (int k = 0; k < 8; k++) {
        const int t = tg * 8 + k;
        float ax = 0.f, ay = 0.f;
#pragma unroll
        for (int j = 0; j <= 2 * WIN; j++) {
            const float w = ew[j];
            const float2 v = *(const float2*)&yt[t + j][cp << 1];
            ax = fmaf(w, v.x, ax);
            ay = fmaf(w, v.y, ay);
        }
        const float iz = invZ[t];
        const float r0 = ax * iz, r1 = ay * iz;
        const __nv_bfloat16 h0 = __float2bfloat16(r0);
        const __nv_bfloat16 h1 = __float2bfloat16(r1);
        const __nv_bfloat16 l0 = __float2bfloat16(r0 - __bfloat162float(h0));
        const __nv_bfloat16 l1 = __float2bfloat16(r1 - __bfloat162float(h1));
        const int n = n0 + t;
        const size_t eo = ((size_t)b * NSEQ + n) * INNER + h * DHEAD + half * 64 + (cp << 1);
        *(__nv_bfloat162*)(shi + eo) = __nv_bfloat162(h0, h1);
        *(__nv_bfloat162*)(slo + eo) = __nv_bfloat162(l0, l1);
    }
}

// ---------------------------------------------------------------------------
extern "C" void kernel_launch(void* const* d_in, const int* in_sizes, int n_in,
                              void* d_out, int out_size) {
    const float* x     = (const float*)d_in[0];
    const float* Wg    = (const float*)d_in[1];
    const float* Wout  = (const float*)d_in[2];
    const float* sigma = (const float*)d_in[3];
    float* out = (float*)d_out;

    float *y; __nv_bfloat16 *xhi, *xlo, *shi, *slo, *wgh, *wgl, *woh, *wol;
    cudaGetSymbolAddress((void**)&y,   g_y);
    cudaGetSymbolAddress((void**)&xhi, g_xhi);
    cudaGetSymbolAddress((void**)&xlo, g_xlo);
    cudaGetSymbolAddress((void**)&shi, g_shi);
    cudaGetSymbolAddress((void**)&slo, g_slo);
    cudaGetSymbolAddress((void**)&wgh, g_wgT_hi);
    cudaGetSymbolAddress((void**)&wgl, g_wgT_lo);
    cudaGetSymbolAddress((void**)&woh, g_woT_hi);
    cudaGetSymbolAddress((void**)&wol, g_woT_lo);

    cudaFuncSetAttribute(gemm_mma, cudaFuncAttributeMaxDynamicSharedMemorySize, SMEM_GEMM);

    // prep: split x, transpose+split weights
    split_kernel<<<(MROWS * DIM / 4 + 255) / 256, 256>>>(x, xhi, xlo, MROWS * DIM / 4);
    transpose_split<<<dim3(INNER / 32, DIM / 32), dim3(32, 8)>>>(Wg, wgh, wgl, DIM, INNER);
    transpose_split<<<dim3(DIM / 32, INNER / 32), dim3(32, 8)>>>(Wout, woh, wol, INNER, DIM);

    // GEMM1: y[8192,1024] = x @ Wg
    gemm_mma<<<dim3(INNER / CTN, MROWS / CTM), 256, SMEM_GEMM>>>(
        xhi, xlo, wgh, wgl, y, MROWS, INNER, DIM);

    // banded Gaussian attention -> s (bf16 split)
    smooth_kernel<<<dim3(NSEQ / TN, 2, BATCH * NHEAD), 256>>>(y, shi, slo, sigma);

    // GEMM2: out[8192,512] = s @ Wout
    gemm_mma<<<dim3(DIM / CTN, MROWS / CTM), 256, SMEM_GEMM>>>(
        shi, slo, woh, wol, out, MROWS, DIM, INNER);
}

// round 5
// speedup vs baseline: 2.0408x; 1.0973x over previous
#include <cuda_runtime.h>
#include <cuda_bf16.h>
#include <cstdint>
#include <cstddef>

// Problem constants
#define BATCH 4
#define NSEQ 2048
#define DIM 512
#define NHEAD 8
#define DHEAD 128
#define INNER 1024
#define MROWS (BATCH*NSEQ)  // 8192

#define WIN 16              // sigma<=2.5: tap at d=17 ~ 9e-11 -> negligible
#define TN 64

// ---------------- scratch (allocation-free rule) ----------------
__device__ __align__(16) float          g_y[MROWS * INNER];
__device__ __align__(16) __nv_bfloat16  g_xhi[MROWS * DIM];
__device__ __align__(16) __nv_bfloat16  g_xlo[MROWS * DIM];
__device__ __align__(16) __nv_bfloat16  g_shi[MROWS * INNER];
__device__ __align__(16) __nv_bfloat16  g_slo[MROWS * INNER];
__device__ __align__(16) __nv_bfloat16  g_wgT_hi[INNER * DIM];   // Wg^T  [1024,512]
__device__ __align__(16) __nv_bfloat16  g_wgT_lo[INNER * DIM];
__device__ __align__(16) __nv_bfloat16  g_woT_hi[DIM * INNER];   // Wout^T [512,1024]
__device__ __align__(16) __nv_bfloat16  g_woT_lo[DIM * INNER];

// ---------------- helpers ----------------
typedef unsigned long long ull;
__device__ __forceinline__ ull pack_dup(float a) {
    ull r; asm("mov.b64 %0, {%1, %1};" : "=l"(r) : "f"(a)); return r;
}
__device__ __forceinline__ void ffma2(ull& d, ull a, ull b) {
    asm("fma.rn.f32x2 %0, %1, %2, %0;" : "+l"(d) : "l"(a), "l"(b));
}
__device__ __forceinline__ void unpack2(ull v, float& lo, float& hi) {
    asm("mov.b64 {%0, %1}, %2;" : "=f"(lo), "=f"(hi) : "l"(v));
}
__device__ __forceinline__ uint32_t smem_to_u32(const void* p) {
    uint32_t a;
    asm("{ .reg .u64 t; cvta.to.shared.u64 t, %1; cvt.u32.u64 %0, t; }" : "=r"(a) : "l"(p));
    return a;
}
__device__ __forceinline__ void cp16(uint32_t dst, const void* src) {
    asm volatile("cp.async.cg.shared.global [%0], [%1], 16;" :: "r"(dst), "l"(src) : "memory");
}
#define CP_COMMIT() asm volatile("cp.async.commit_group;" ::: "memory")
#define CP_WAIT1()  asm volatile("cp.async.wait_group 1;" ::: "memory")

__device__ __forceinline__ void ldsm_x4(uint32_t addr, uint32_t& r0, uint32_t& r1,
                                        uint32_t& r2, uint32_t& r3) {
    asm volatile("ldmatrix.sync.aligned.m8n8.x4.shared.b16 {%0,%1,%2,%3}, [%4];"
                 : "=r"(r0), "=r"(r1), "=r"(r2), "=r"(r3) : "r"(addr));
}
__device__ __forceinline__ void mma16816(float* d, const uint32_t* a,
                                         uint32_t b0, uint32_t b1) {
    asm volatile("mma.sync.aligned.m16n8k16.row.col.f32.bf16.bf16.f32 "
                 "{%0,%1,%2,%3}, {%4,%5,%6,%7}, {%8,%9}, {%0,%1,%2,%3};"
                 : "+f"(d[0]), "+f"(d[1]), "+f"(d[2]), "+f"(d[3])
                 : "r"(a[0]), "r"(a[1]), "r"(a[2]), "r"(a[3]), "r"(b0), "r"(b1));
}

// ---------------------------------------------------------------------------
// HMMA GEMM: C[M,N](f32) = (Ahi+Alo)[M,K] @ (Bhi+Blo)^T,  B* stored [N,K].
// CTA tile 128x64, K-chunk 32, 8 warps, warp tile 32x32.
// Products hi*hi + hi*lo + lo*hi in f32 registers.
// 3-stage cp.async pipeline, ONE __syncthreads per K-chunk.
// ---------------------------------------------------------------------------
#define CTM 128
#define CTN 64
#define TK  32
#define ROWB 80
#define STG_A (CTM * ROWB)                   // 10240
#define STG_B (CTN * ROWB)                   // 5120
#define STAGE_BYTES (2 * STG_A + 2 * STG_B)  // 30720
#define NSTAGE 3
#define SMEM_GEMM (NSTAGE * STAGE_BYTES)     // 92160

__global__ __launch_bounds__(256, 2)
void gemm_mma(const __nv_bfloat16* __restrict__ Ahi, const __nv_bfloat16* __restrict__ Alo,
              const __nv_bfloat16* __restrict__ Bhi, const __nv_bfloat16* __restrict__ Blo,
              float* __restrict__ C, int M, int N, int K) {
    extern __shared__ char smem[];
    const uint32_t sb = smem_to_u32(smem);
    const int tid = threadIdx.x;
    const int wid = tid >> 5;
    const int lane = tid & 31;
    const int row0 = blockIdx.y << 7;
    const int col0 = blockIdx.x << 6;

    const int wm = wid & 3;
    const int wn = wid >> 2;
    const int m0 = wm << 5;
    const int n0 = wn << 5;

    const int arow = tid >> 2;
    const int ac   = (tid & 3) << 3;
    const int acB  = (tid & 3) << 4;

    auto load_stage = [&](int buf, int kc) {
        const uint32_t st = sb + buf * STAGE_BYTES;
#pragma unroll
        for (int r = 0; r < 2; r++) {
            const int row = arow + 64 * r;
            const uint32_t d = st + row * ROWB + acB;
            const size_t e = (size_t)(row0 + row) * K + kc + ac;
            cp16(d, Ahi + e);
            cp16(d + STG_A, Alo + e);
        }
        {
            const uint32_t d = st + 2 * STG_A + arow * ROWB + acB;
            const size_t e = (size_t)(col0 + arow) * K + kc + ac;
            cp16(d, Bhi + e);
            cp16(d + STG_B, Blo + e);
        }
    };

    float d[2][4][4];
#pragma unroll
    for (int i = 0; i < 2; i++)
#pragma unroll
        for (int j = 0; j < 4; j++)
#pragma unroll
            for (int q = 0; q < 4; q++) d[i][j][q] = 0.f;

    const int KT = K / TK;
    load_stage(0, 0);  CP_COMMIT();
    load_stage(1, TK); CP_COMMIT();

    const uint32_t a_lane_off = (uint32_t)((lane & 15) * ROWB + ((lane >> 4) << 4));
    const uint32_t b_lane_off = (uint32_t)((((lane >> 4) << 3) + (lane & 7)) * ROWB
                                           + (((lane >> 3) & 1) << 4));

    int cur = 0;        // kt % 3
    int nxt2 = 2;       // (kt+2) % 3
    for (int kt = 0; kt < KT; kt++) {
        CP_WAIT1();          // stage kt resident (kt+1 may be in flight)
        __syncthreads();     // everyone done with the buffer we're about to refill

        if (kt + 2 < KT) load_stage(nxt2, (kt + 2) * TK);
        CP_COMMIT();         // one group per iter (possibly empty) keeps the count exact

        const uint32_t st = sb + cur * STAGE_BYTES;
#pragma unroll
        for (int s = 0; s < 2; s++) {
            uint32_t ah[2][4], al[2][4], bh[2][4], bl[2][4];
#pragma unroll
            for (int i = 0; i < 2; i++) {
                const uint32_t aa = st + (uint32_t)((m0 + i * 16) * ROWB + s * 32) + a_lane_off;
                ldsm_x4(aa, ah[i][0], ah[i][1], ah[i][2], ah[i][3]);
                ldsm_x4(aa + STG_A, al[i][0], al[i][1], al[i][2], al[i][3]);
            }
#pragma unroll
            for (int g = 0; g < 2; g++) {
                const uint32_t ba = st + 2 * STG_A
                                  + (uint32_t)((n0 + g * 16) * ROWB + s * 32) + b_lane_off;
                ldsm_x4(ba, bh[g][0], bh[g][1], bh[g][2], bh[g][3]);
                ldsm_x4(ba + STG_B, bl[g][0], bl[g][1], bl[g][2], bl[g][3]);
            }
#pragma unroll
            for (int i = 0; i < 2; i++)
#pragma unroll
                for (int g = 0; g < 2; g++)
#pragma unroll
                    for (int jj = 0; jj < 2; jj++) {
                        const int j = g * 2 + jj;
                        mma16816(d[i][j], ah[i], bh[g][jj * 2], bh[g][jj * 2 + 1]);
                        mma16816(d[i][j], ah[i], bl[g][jj * 2], bl[g][jj * 2 + 1]);
                        mma16816(d[i][j], al[i], bh[g][jj * 2], bh[g][jj * 2 + 1]);
                    }
        }
        cur  = (cur == 2)  ? 0 : cur + 1;
        nxt2 = (nxt2 == 2) ? 0 : nxt2 + 1;
    }

    // epilogue
    const int gr = lane >> 2;
    const int tg = lane & 3;
#pragma unroll
    for (int i = 0; i < 2; i++) {
        const int r0 = row0 + m0 + i * 16 + gr;
#pragma unroll
        for (int j = 0; j < 4; j++) {
            const int c = col0 + n0 + j * 8 + tg * 2;
            *(float2*)&C[(size_t)r0 * N + c]       = make_float2(d[i][j][0], d[i][j][1]);
            *(float2*)&C[(size_t)(r0 + 8) * N + c] = make_float2(d[i][j][2], d[i][j][3]);
        }
    }
}

// ---------------------------------------------------------------------------
// fp32 -> (hi, lo) bf16 split, vectorized
// ---------------------------------------------------------------------------
__global__ __launch_bounds__(256)
void split_kernel(const float* __restrict__ in, __nv_bfloat16* __restrict__ hi,
                  __nv_bfloat16* __restrict__ lo, int n4) {
    const int i = blockIdx.x * 256 + threadIdx.x;
    if (i >= n4) return;
    const float4 v = ((const float4*)in)[i];
    float f[4] = {v.x, v.y, v.z, v.w};
    __nv_bfloat16 h[4], l[4];
#pragma unroll
    for (int j = 0; j < 4; j++) {
        h[j] = __float2bfloat16(f[j]);
        l[j] = __float2bfloat16(f[j] - __bfloat162float(h[j]));
    }
    ((__nv_bfloat162*)hi)[2 * i]     = __nv_bfloat162(h[0], h[1]);
    ((__nv_bfloat162*)hi)[2 * i + 1] = __nv_bfloat162(h[2], h[3]);
    ((__nv_bfloat162*)lo)[2 * i]     = __nv_bfloat162(l[0], l[1]);
    ((__nv_bfloat162*)lo)[2 * i + 1] = __nv_bfloat162(l[2], l[3]);
}

// ---------------------------------------------------------------------------
// W[K,N] f32 -> W^T hi/lo bf16 [N,K]
// ---------------------------------------------------------------------------
__global__ __launch_bounds__(256)
void transpose_split(const float* __restrict__ in, __nv_bfloat16* __restrict__ hiT,
                     __nv_bfloat16* __restrict__ loT, int K, int N) {
    __shared__ float t[32][33];
    const int tx = threadIdx.x, ty = threadIdx.y;
    const int n0 = blockIdx.x * 32, k0 = blockIdx.y * 32;
#pragma unroll
    for (int i = 0; i < 4; i++)
        t[ty + 8 * i][tx] = in[(size_t)(k0 + ty + 8 * i) * N + n0 + tx];
    __syncthreads();
#pragma unroll
    for (int i = 0; i < 4; i++) {
        const float v = t[tx][ty + 8 * i];
        const __nv_bfloat16 h = __float2bfloat16(v);
        const __nv_bfloat16 l = __float2bfloat16(v - __bfloat162float(h));
        const size_t o = (size_t)(n0 + ty + 8 * i) * K + k0 + tx;
        hiT[o] = h;
        loT[o] = l;
    }
}

// ---------------------------------------------------------------------------
// Gaussian banded smoothing (WIN=16, 33 taps), row-normalized, f32x2 packed;
// emits bf16 hi/lo split directly.
// ---------------------------------------------------------------------------
__global__ __launch_bounds__(256)
void smooth_kernel(const float* __restrict__ y, __nv_bfloat16* __restrict__ shi,
                   __nv_bfloat16* __restrict__ slo, const float* __restrict__ sigma) {
    __shared__ float yt[TN + 2 * WIN][64];   // 96 x 64
    __shared__ float ew[2 * WIN + 1];        // 33 taps
    __shared__ float invZ[TN];

    const int n0 = blockIdx.x * TN;
    const int half = blockIdx.y;
    const int bh = blockIdx.z;
    const int b = bh >> 3;
    const int h = bh & 7;
    const int tid = threadIdx.x;

    const float* ybase = y + (size_t)b * NSEQ * INNER + h * DHEAD + half * 64;
    for (int i = tid; i < (TN + 2 * WIN) * 16; i += 256) {
        const int r = i >> 4;
        const int c = (i & 15) << 2;
        const int m = n0 - WIN + r;
        float4 v = make_float4(0.f, 0.f, 0.f, 0.f);
        if (m >= 0 && m < NSEQ) v = *(const float4*)(ybase + (size_t)m * INNER + c);
        *(float4*)&yt[r][c] = v;
    }
    if (tid < 2 * WIN + 1) {
        const float sg = sigma[h];
        const float dd = (float)(tid - WIN);
        ew[tid] = __expf(-dd * dd / (2.f * sg * sg));
    }
    __syncthreads();
    if (tid < TN) {
        const int n = n0 + tid;
        float z = 0.f;
#pragma unroll
        for (int j = 0; j <= 2 * WIN; j++) {
            const int m = n - WIN + j;
            if (m >= 0 && m < NSEQ) z += ew[j];
        }
        invZ[tid] = 1.f / z;
    }
    __syncthreads();

    const int cp = tid & 31;     // channel pair
    const int tg = tid >> 5;     // 0..7
#pragma unroll
    for (int k = 0; k < 8; k++) {
        const int t = tg * 8 + k;
        ull acc = 0ULL;
#pragma unroll
        for (int j = 0; j <= 2 * WIN; j++) {
            const ull w = pack_dup(ew[j]);
            const ull v = *(const ull*)&yt[t + j][cp << 1];
            ffma2(acc, w, v);
        }
        float ax, ay;
        unpack2(acc, ax, ay);
        const float iz = invZ[t];
        const float r0 = ax * iz, r1 = ay * iz;
        const __nv_bfloat16 h0 = __float2bfloat16(r0);
        const __nv_bfloat16 h1 = __float2bfloat16(r1);
        const __nv_bfloat16 l0 = __float2bfloat16(r0 - __bfloat162float(h0));
        const __nv_bfloat16 l1 = __float2bfloat16(r1 - __bfloat162float(h1));
        const int n = n0 + t;
        const size_t eo = ((size_t)b * NSEQ + n) * INNER + h * DHEAD + half * 64 + (cp << 1);
        *(__nv_bfloat162*)(shi + eo) = __nv_bfloat162(h0, h1);
        *(__nv_bfloat162*)(slo + eo) = __nv_bfloat162(l0, l1);
    }
}

// ---------------------------------------------------------------------------
extern "C" void kernel_launch(void* const* d_in, const int* in_sizes, int n_in,
                              void* d_out, int out_size) {
    const float* x     = (const float*)d_in[0];
    const float* Wg    = (const float*)d_in[1];
    const float* Wout  = (const float*)d_in[2];
    const float* sigma = (const float*)d_in[3];
    float* out = (float*)d_out;

    float *y; __nv_bfloat16 *xhi, *xlo, *shi, *slo, *wgh, *wgl, *woh, *wol;
    cudaGetSymbolAddress((void**)&y,   g_y);
    cudaGetSymbolAddress((void**)&xhi, g_xhi);
    cudaGetSymbolAddress((void**)&xlo, g_xlo);
    cudaGetSymbolAddress((void**)&shi, g_shi);
    cudaGetSymbolAddress((void**)&slo, g_slo);
    cudaGetSymbolAddress((void**)&wgh, g_wgT_hi);
    cudaGetSymbolAddress((void**)&wgl, g_wgT_lo);
    cudaGetSymbolAddress((void**)&woh, g_woT_hi);
    cudaGetSymbolAddress((void**)&wol, g_woT_lo);

    cudaFuncSetAttribute(gemm_mma, cudaFuncAttributeMaxDynamicSharedMemorySize, SMEM_GEMM);

    split_kernel<<<(MROWS * DIM / 4 + 255) / 256, 256>>>(x, xhi, xlo, MROWS * DIM / 4);
    transpose_split<<<dim3(INNER / 32, DIM / 32), dim3(32, 8)>>>(Wg, wgh, wgl, DIM, INNER);
    transpose_split<<<dim3(DIM / 32, INNER / 32), dim3(32, 8)>>>(Wout, woh, wol, INNER, DIM);

    gemm_mma<<<dim3(INNER / CTN, MROWS / CTM), 256, SMEM_GEMM>>>(
        xhi, xlo, wgh, wgl, y, MROWS, INNER, DIM);

    smooth_kernel<<<dim3(NSEQ / TN, 2, BATCH * NHEAD), 256>>>(y, shi, slo, sigma);

    gemm_mma<<<dim3(DIM / CTN, MROWS / CTM), 256, SMEM_GEMM>>>(
        shi, slo, woh, wol, out, MROWS, DIM, INNER);
}